// round 2
// baseline (speedup 1.0000x reference)
#include <cuda_runtime.h>
#include <math.h>

#define S_LEN 32
#define T_LEN 32
#define BATCH 64
#define HID   512
#define BH    (BATCH * HID)        // 32768 floats per [B,H] slab
#define Z4    (BATCH * 4 * HID)    // 131072 floats per [B,4H] slab
#define MAXC  32

// ---------------- persistent device scratch (allocation-free rule) ----------
__device__ __align__(16) float g_s_x[S_LEN * BH];
__device__ __align__(16) float g_s_h[S_LEN * BH];
__device__ __align__(16) float g_s_m[S_LEN * BH];
__device__ __align__(16) float g_t_x[T_LEN * BH];
__device__ __align__(16) float g_t_h[T_LEN * BH];
__device__ __align__(16) float g_t_m[T_LEN * BH];
__device__ __align__(16) float g_hmid[MAXC * BH];
__device__ __align__(16) float g_r  [MAXC * Z4];
__device__ __align__(16) float g_zs [MAXC * Z4];
__device__ __align__(16) float g_zt [MAXC * Z4];

// ---------------- 64x128 fp32x2 GEMM tile, 256 threads, BK=32 ---------------
// C[64, n0:n0+128] = A[64,K] @ W[K,N] (+bias). A row stride fixed 512.
// A may be a K-concat of two [64,512] slabs (A0 then A1).
// Inner loop uses packed fma.rn.f32x2 (2 MACs/issue on sm_103a).
__device__ __forceinline__ void gemm64x128(
    const float* __restrict__ A0, const float* __restrict__ A1,
    int K, const float* __restrict__ W, int ldw,
    float* __restrict__ C, int ldc,
    const float* __restrict__ bias, int n0)
{
    __shared__ __align__(16) float As[32][64];    // [k][m]
    __shared__ __align__(16) float Ws[32][128];   // [k][n]

    const int tid = threadIdx.x;
    const int tx  = tid & 15;   // n group: 8 cols  (4 f32x2 pairs)
    const int ty  = tid >> 4;   // m group: 4 rows

    unsigned long long acc[4][4];   // [m][n-pair], each = packed float2
#pragma unroll
    for (int a = 0; a < 4; a++)
#pragma unroll
        for (int b = 0; b < 4; b++) acc[a][b] = 0ull;

    for (int k0 = 0; k0 < K; k0 += 32) {
        const float* Ab = (k0 < 512) ? (A0 + k0) : (A1 + (k0 - 512));

        // A tile: 64 rows x 32 k = 512 float4, 2 per thread, transpose into As[k][m]
#pragma unroll
        for (int r = 0; r < 2; r++) {
            int idx  = tid + r * 256;          // 0..511
            int la_m = idx >> 3;               // 0..63
            int la_k = (idx & 7) * 4;          // 0..28
            float4 v = *reinterpret_cast<const float4*>(Ab + la_m * 512 + la_k);
            As[la_k + 0][la_m] = v.x;
            As[la_k + 1][la_m] = v.y;
            As[la_k + 2][la_m] = v.z;
            As[la_k + 3][la_m] = v.w;
        }
        // W tile: 32 k x 128 n = 1024 float4, 4 per thread, direct copy
#pragma unroll
        for (int r = 0; r < 4; r++) {
            int idx  = tid + r * 256;          // 0..1023
            int lw_k = idx >> 5;               // 0..31
            int lw_n = (idx & 31) * 4;         // 0..124
            float4 v = *reinterpret_cast<const float4*>(
                W + (size_t)(k0 + lw_k) * ldw + n0 + lw_n);
            *reinterpret_cast<float4*>(&Ws[lw_k][lw_n]) = v;
        }
        __syncthreads();

#pragma unroll 8
        for (int kk = 0; kk < 32; kk++) {
            float4 a4 = *reinterpret_cast<const float4*>(&As[kk][ty * 4]);
            ulonglong2 wlo = *reinterpret_cast<const ulonglong2*>(&Ws[kk][tx * 8]);
            ulonglong2 whi = *reinterpret_cast<const ulonglong2*>(&Ws[kk][tx * 8 + 4]);
            unsigned long long wp[4] = {wlo.x, wlo.y, whi.x, whi.y};

            unsigned long long ad[4];
            asm("mov.b64 %0, {%1, %1};" : "=l"(ad[0]) : "f"(a4.x));
            asm("mov.b64 %0, {%1, %1};" : "=l"(ad[1]) : "f"(a4.y));
            asm("mov.b64 %0, {%1, %1};" : "=l"(ad[2]) : "f"(a4.z));
            asm("mov.b64 %0, {%1, %1};" : "=l"(ad[3]) : "f"(a4.w));

#pragma unroll
            for (int im = 0; im < 4; im++)
#pragma unroll
                for (int ip = 0; ip < 4; ip++)
                    asm("fma.rn.f32x2 %0, %1, %2, %0;"
                        : "+l"(acc[im][ip]) : "l"(ad[im]), "l"(wp[ip]));
        }
        __syncthreads();
    }

    const int mBase = ty * 4;
    const int nBase = n0 + tx * 8;
    float b8[8] = {0,0,0,0,0,0,0,0};
    if (bias) {
        float4 b0 = *reinterpret_cast<const float4*>(bias + nBase);
        float4 b1 = *reinterpret_cast<const float4*>(bias + nBase + 4);
        b8[0]=b0.x; b8[1]=b0.y; b8[2]=b0.z; b8[3]=b0.w;
        b8[4]=b1.x; b8[5]=b1.y; b8[6]=b1.z; b8[7]=b1.w;
    }
#pragma unroll
    for (int im = 0; im < 4; im++) {
        float o[8];
#pragma unroll
        for (int ip = 0; ip < 4; ip++) {
            float lo, hi;
            asm("mov.b64 {%0, %1}, %2;" : "=f"(lo), "=f"(hi) : "l"(acc[im][ip]));
            o[ip * 2]     = lo + b8[ip * 2];
            o[ip * 2 + 1] = hi + b8[ip * 2 + 1];
        }
        float* Crow = C + (size_t)(mBase + im) * ldc + nBase;
        *reinterpret_cast<float4*>(Crow)     = make_float4(o[0], o[1], o[2], o[3]);
        *reinterpret_cast<float4*>(Crow + 4) = make_float4(o[4], o[5], o[6], o[7]);
    }
}

// ---------------- kernels ----------------------------------------------------
__global__ void k_init(const float* __restrict__ src, const float* __restrict__ tgt)
{
    int idx = blockIdx.x * blockDim.x + threadIdx.x;
    g_s_x[idx] = src[idx];
    g_s_h[idx] = 0.f;
    g_s_m[idx] = 0.f;
    g_t_x[idx] = tgt[idx];
    g_t_h[idx] = 0.f;
    g_t_m[idx] = 0.f;
}

// Phase A: hmid = concat(s_h[i], t_h[j]) @ W_H2h + b_H2h
__global__ __launch_bounds__(256) void k_hmid(
    int d, int i_lo,
    const float* __restrict__ W_H2h, const float* __restrict__ b_H2h)
{
    const int ci = blockIdx.x;
    const int i  = i_lo + ci;
    const int j  = d - i;
    gemm64x128(g_s_h + (size_t)i * BH, g_t_h + (size_t)j * BH, 1024,
               W_H2h, HID, g_hmid + (size_t)ci * BH, HID, b_H2h, blockIdx.y * 128);
}

// Phase B: r = hmid@W_rec ; zs = s_x@W_kernel ; zt = t_x@W_kernel
__global__ __launch_bounds__(256) void k_zmat(
    int d, int i_lo,
    const float* __restrict__ Wk, const float* __restrict__ Wr)
{
    const int ci = blockIdx.x;
    const int i  = i_lo + ci;
    const int j  = d - i;
    const float* A;
    const float* W;
    float* C;
    if (blockIdx.z == 0)      { A = g_hmid + (size_t)ci * BH; W = Wr; C = g_r  + (size_t)ci * Z4; }
    else if (blockIdx.z == 1) { A = g_s_x  + (size_t)i  * BH; W = Wk; C = g_zs + (size_t)ci * Z4; }
    else                      { A = g_t_x  + (size_t)j  * BH; W = Wk; C = g_zt + (size_t)ci * Z4; }
    gemm64x128(A, A, 512, W, 4 * HID, C, 4 * HID, nullptr, blockIdx.y * 128);
}

__device__ __forceinline__ float sigmoidf(float x) { return 1.f / (1.f + __expf(-x)); }

// Phase C: gates + state update (+ final outputs)
__global__ __launch_bounds__(256) void k_gate(
    int d, int i_lo, const float* __restrict__ b_lstm, float* __restrict__ out)
{
    const int ci  = blockIdx.x;
    const int i   = i_lo + ci;
    const int j   = d - i;
    const int idx = blockIdx.y * blockDim.x + threadIdx.x;
    const int m   = idx >> 9;
    const int h   = idx & 511;

    const size_t base = (size_t)ci * Z4 + (size_t)m * (4 * HID);
    const float bi = b_lstm[h];
    const float bf = b_lstm[HID + h];
    const float bg = b_lstm[2 * HID + h];
    const float bo = b_lstm[3 * HID + h];
    const float rI = g_r[base + h];
    const float rF = g_r[base + HID + h];
    const float rG = g_r[base + 2 * HID + h];
    const float rO = g_r[base + 3 * HID + h];

    {
        const float zi = g_zs[base + h]           + rI + bi;
        const float zf = g_zs[base + HID + h]     + rF + bf;
        const float zg = g_zs[base + 2 * HID + h] + rG + bg;
        const float zo = g_zs[base + 3 * HID + h] + rO + bo;
        const size_t si = (size_t)i * BH + idx;
        const float c  = g_s_m[si];
        const float c2 = sigmoidf(zf) * c + sigmoidf(zi) * tanhf(zg);
        const float h2 = sigmoidf(zo) * tanhf(c2);
        g_s_m[si] = c2;
        g_s_h[si] = h2;
        g_s_x[si] = h2;
        if (j == T_LEN - 1) out[si] = h2;
    }
    {
        const float zi = g_zt[base + h]           + rI + bi;
        const float zf = g_zt[base + HID + h]     + rF + bf;
        const float zg = g_zt[base + 2 * HID + h] + rG + bg;
        const float zo = g_zt[base + 3 * HID + h] + rO + bo;
        const size_t ti = (size_t)j * BH + idx;
        const float c  = g_t_m[ti];
        const float c2 = sigmoidf(zf) * c + sigmoidf(zi) * tanhf(zg);
        const float h2 = sigmoidf(zo) * tanhf(c2);
        g_t_m[ti] = c2;
        g_t_h[ti] = h2;
        g_t_x[ti] = h2;
        if (i == S_LEN - 1) out[(size_t)S_LEN * BH + ti] = h2;
    }
}

// ---------------- launch -----------------------------------------------------
extern "C" void kernel_launch(void* const* d_in, const int* in_sizes, int n_in,
                              void* d_out, int out_size)
{
    const float* source = (const float*)d_in[0];
    const float* target = (const float*)d_in[1];
    const float* W_H2h  = (const float*)d_in[2];
    const float* b_H2h  = (const float*)d_in[3];
    const float* Wk     = (const float*)d_in[4];
    const float* Wr     = (const float*)d_in[5];
    const float* b_lstm = (const float*)d_in[6];
    float* out = (float*)d_out;

    k_init<<<(S_LEN * BH) / 256, 256>>>(source, target);

    for (int d = 0; d < S_LEN + T_LEN - 1; d++) {
        int i_lo = d - (T_LEN - 1); if (i_lo < 0) i_lo = 0;
        int i_hi = d; if (i_hi > S_LEN - 1) i_hi = S_LEN - 1;
        int nc = i_hi - i_lo + 1;
        k_hmid<<<dim3(nc, HID / 128), 256>>>(d, i_lo, W_H2h, b_H2h);
        k_zmat<<<dim3(nc, (4 * HID) / 128, 3), 256>>>(d, i_lo, Wk, Wr);
        k_gate<<<dim3(nc, BH / 256), 256>>>(d, i_lo, b_lstm, out);
    }
}

// round 3
// speedup vs baseline: 1.0007x; 1.0007x over previous
#include <cuda_runtime.h>
#include <math.h>

#define S_LEN 32
#define T_LEN 32
#define BATCH 64
#define HID   512
#define BH    (BATCH * HID)        // 32768 floats per [B,H] slab
#define Z4    (BATCH * 4 * HID)    // 131072 floats per [B,4H] slab
#define MAXC  32

// ---------------- persistent device scratch (allocation-free rule) ----------
__device__ __align__(16) float g_s_x[S_LEN * BH];
__device__ __align__(16) float g_s_h[S_LEN * BH];
__device__ __align__(16) float g_s_m[S_LEN * BH];
__device__ __align__(16) float g_t_x[T_LEN * BH];
__device__ __align__(16) float g_t_h[T_LEN * BH];
__device__ __align__(16) float g_t_m[T_LEN * BH];
__device__ __align__(16) float g_hmid[MAXC * BH];
__device__ __align__(16) float g_r  [MAXC * Z4];
__device__ __align__(16) float g_zs [MAXC * Z4];
__device__ __align__(16) float g_zt [MAXC * Z4];

// ---------------- 64x128 fp32x2 GEMM tile, 256 threads, BK=32 ---------------
// C[64, n0:n0+128] = A[64,K] @ W[K,N] (+bias). A row stride fixed 512.
// A may be a K-concat of two [64,512] slabs (A0 then A1).
// Inner loop uses packed fma.rn.f32x2 (2 MACs/issue on sm_103a).
__device__ __forceinline__ void gemm64x128(
    const float* __restrict__ A0, const float* __restrict__ A1,
    int K, const float* __restrict__ W, int ldw,
    float* __restrict__ C, int ldc,
    const float* __restrict__ bias, int n0)
{
    __shared__ __align__(16) float As[32][64];    // [k][m]
    __shared__ __align__(16) float Ws[32][128];   // [k][n]

    const int tid = threadIdx.x;
    const int tx  = tid & 15;   // n group: 8 cols  (4 f32x2 pairs)
    const int ty  = tid >> 4;   // m group: 4 rows

    unsigned long long acc[4][4];   // [m][n-pair], each = packed float2
#pragma unroll
    for (int a = 0; a < 4; a++)
#pragma unroll
        for (int b = 0; b < 4; b++) acc[a][b] = 0ull;

    for (int k0 = 0; k0 < K; k0 += 32) {
        const float* Ab = (k0 < 512) ? (A0 + k0) : (A1 + (k0 - 512));

        // A tile: 64 rows x 32 k = 512 float4, 2 per thread, transpose into As[k][m]
#pragma unroll
        for (int r = 0; r < 2; r++) {
            int idx  = tid + r * 256;          // 0..511
            int la_m = idx >> 3;               // 0..63
            int la_k = (idx & 7) * 4;          // 0..28
            float4 v = *reinterpret_cast<const float4*>(Ab + la_m * 512 + la_k);
            As[la_k + 0][la_m] = v.x;
            As[la_k + 1][la_m] = v.y;
            As[la_k + 2][la_m] = v.z;
            As[la_k + 3][la_m] = v.w;
        }
        // W tile: 32 k x 128 n = 1024 float4, 4 per thread, direct copy
#pragma unroll
        for (int r = 0; r < 4; r++) {
            int idx  = tid + r * 256;          // 0..1023
            int lw_k = idx >> 5;               // 0..31
            int lw_n = (idx & 31) * 4;         // 0..124
            float4 v = *reinterpret_cast<const float4*>(
                W + (size_t)(k0 + lw_k) * ldw + n0 + lw_n);
            *reinterpret_cast<float4*>(&Ws[lw_k][lw_n]) = v;
        }
        __syncthreads();

#pragma unroll 8
        for (int kk = 0; kk < 32; kk++) {
            float4 a4 = *reinterpret_cast<const float4*>(&As[kk][ty * 4]);
            ulonglong2 wlo = *reinterpret_cast<const ulonglong2*>(&Ws[kk][tx * 8]);
            ulonglong2 whi = *reinterpret_cast<const ulonglong2*>(&Ws[kk][tx * 8 + 4]);
            unsigned long long wp[4] = {wlo.x, wlo.y, whi.x, whi.y};

            unsigned long long ad[4];
            asm("mov.b64 %0, {%1, %1};" : "=l"(ad[0]) : "f"(a4.x));
            asm("mov.b64 %0, {%1, %1};" : "=l"(ad[1]) : "f"(a4.y));
            asm("mov.b64 %0, {%1, %1};" : "=l"(ad[2]) : "f"(a4.z));
            asm("mov.b64 %0, {%1, %1};" : "=l"(ad[3]) : "f"(a4.w));

#pragma unroll
            for (int im = 0; im < 4; im++)
#pragma unroll
                for (int ip = 0; ip < 4; ip++)
                    asm("fma.rn.f32x2 %0, %1, %2, %0;"
                        : "+l"(acc[im][ip]) : "l"(ad[im]), "l"(wp[ip]));
        }
        __syncthreads();
    }

    const int mBase = ty * 4;
    const int nBase = n0 + tx * 8;
    float b8[8] = {0,0,0,0,0,0,0,0};
    if (bias) {
        float4 b0 = *reinterpret_cast<const float4*>(bias + nBase);
        float4 b1 = *reinterpret_cast<const float4*>(bias + nBase + 4);
        b8[0]=b0.x; b8[1]=b0.y; b8[2]=b0.z; b8[3]=b0.w;
        b8[4]=b1.x; b8[5]=b1.y; b8[6]=b1.z; b8[7]=b1.w;
    }
#pragma unroll
    for (int im = 0; im < 4; im++) {
        float o[8];
#pragma unroll
        for (int ip = 0; ip < 4; ip++) {
            float lo, hi;
            asm("mov.b64 {%0, %1}, %2;" : "=f"(lo), "=f"(hi) : "l"(acc[im][ip]));
            o[ip * 2]     = lo + b8[ip * 2];
            o[ip * 2 + 1] = hi + b8[ip * 2 + 1];
        }
        float* Crow = C + (size_t)(mBase + im) * ldc + nBase;
        *reinterpret_cast<float4*>(Crow)     = make_float4(o[0], o[1], o[2], o[3]);
        *reinterpret_cast<float4*>(Crow + 4) = make_float4(o[4], o[5], o[6], o[7]);
    }
}

// ---------------- kernels ----------------------------------------------------
__global__ void k_init(const float* __restrict__ src, const float* __restrict__ tgt)
{
    int idx = blockIdx.x * blockDim.x + threadIdx.x;
    g_s_x[idx] = src[idx];
    g_s_h[idx] = 0.f;
    g_s_m[idx] = 0.f;
    g_t_x[idx] = tgt[idx];
    g_t_h[idx] = 0.f;
    g_t_m[idx] = 0.f;
}

// Phase A: hmid = concat(s_h[i], t_h[j]) @ W_H2h + b_H2h
__global__ __launch_bounds__(256) void k_hmid(
    int d, int i_lo,
    const float* __restrict__ W_H2h, const float* __restrict__ b_H2h)
{
    const int ci = blockIdx.x;
    const int i  = i_lo + ci;
    const int j  = d - i;
    gemm64x128(g_s_h + (size_t)i * BH, g_t_h + (size_t)j * BH, 1024,
               W_H2h, HID, g_hmid + (size_t)ci * BH, HID, b_H2h, blockIdx.y * 128);
}

// Phase B: r = hmid@W_rec ; zs = s_x@W_kernel ; zt = t_x@W_kernel
__global__ __launch_bounds__(256) void k_zmat(
    int d, int i_lo,
    const float* __restrict__ Wk, const float* __restrict__ Wr)
{
    const int ci = blockIdx.x;
    const int i  = i_lo + ci;
    const int j  = d - i;
    const float* A;
    const float* W;
    float* C;
    if (blockIdx.z == 0)      { A = g_hmid + (size_t)ci * BH; W = Wr; C = g_r  + (size_t)ci * Z4; }
    else if (blockIdx.z == 1) { A = g_s_x  + (size_t)i  * BH; W = Wk; C = g_zs + (size_t)ci * Z4; }
    else                      { A = g_t_x  + (size_t)j  * BH; W = Wk; C = g_zt + (size_t)ci * Z4; }
    gemm64x128(A, A, 512, W, 4 * HID, C, 4 * HID, nullptr, blockIdx.y * 128);
}

__device__ __forceinline__ float sigmoidf(float x) { return 1.f / (1.f + __expf(-x)); }

// Phase C: gates + state update (+ final outputs)
__global__ __launch_bounds__(256) void k_gate(
    int d, int i_lo, const float* __restrict__ b_lstm, float* __restrict__ out)
{
    const int ci  = blockIdx.x;
    const int i   = i_lo + ci;
    const int j   = d - i;
    const int idx = blockIdx.y * blockDim.x + threadIdx.x;
    const int m   = idx >> 9;
    const int h   = idx & 511;

    const size_t base = (size_t)ci * Z4 + (size_t)m * (4 * HID);
    const float bi = b_lstm[h];
    const float bf = b_lstm[HID + h];
    const float bg = b_lstm[2 * HID + h];
    const float bo = b_lstm[3 * HID + h];
    const float rI = g_r[base + h];
    const float rF = g_r[base + HID + h];
    const float rG = g_r[base + 2 * HID + h];
    const float rO = g_r[base + 3 * HID + h];

    {
        const float zi = g_zs[base + h]           + rI + bi;
        const float zf = g_zs[base + HID + h]     + rF + bf;
        const float zg = g_zs[base + 2 * HID + h] + rG + bg;
        const float zo = g_zs[base + 3 * HID + h] + rO + bo;
        const size_t si = (size_t)i * BH + idx;
        const float c  = g_s_m[si];
        const float c2 = sigmoidf(zf) * c + sigmoidf(zi) * tanhf(zg);
        const float h2 = sigmoidf(zo) * tanhf(c2);
        g_s_m[si] = c2;
        g_s_h[si] = h2;
        g_s_x[si] = h2;
        if (j == T_LEN - 1) out[si] = h2;
    }
    {
        const float zi = g_zt[base + h]           + rI + bi;
        const float zf = g_zt[base + HID + h]     + rF + bf;
        const float zg = g_zt[base + 2 * HID + h] + rG + bg;
        const float zo = g_zt[base + 3 * HID + h] + rO + bo;
        const size_t ti = (size_t)j * BH + idx;
        const float c  = g_t_m[ti];
        const float c2 = sigmoidf(zf) * c + sigmoidf(zi) * tanhf(zg);
        const float h2 = sigmoidf(zo) * tanhf(c2);
        g_t_m[ti] = c2;
        g_t_h[ti] = h2;
        g_t_x[ti] = h2;
        if (i == S_LEN - 1) out[(size_t)S_LEN * BH + ti] = h2;
    }
}

// ---------------- launch -----------------------------------------------------
extern "C" void kernel_launch(void* const* d_in, const int* in_sizes, int n_in,
                              void* d_out, int out_size)
{
    const float* source = (const float*)d_in[0];
    const float* target = (const float*)d_in[1];
    const float* W_H2h  = (const float*)d_in[2];
    const float* b_H2h  = (const float*)d_in[3];
    const float* Wk     = (const float*)d_in[4];
    const float* Wr     = (const float*)d_in[5];
    const float* b_lstm = (const float*)d_in[6];
    float* out = (float*)d_out;

    k_init<<<(S_LEN * BH) / 256, 256>>>(source, target);

    for (int d = 0; d < S_LEN + T_LEN - 1; d++) {
        int i_lo = d - (T_LEN - 1); if (i_lo < 0) i_lo = 0;
        int i_hi = d; if (i_hi > S_LEN - 1) i_hi = S_LEN - 1;
        int nc = i_hi - i_lo + 1;
        k_hmid<<<dim3(nc, HID / 128), 256>>>(d, i_lo, W_H2h, b_H2h);
        k_zmat<<<dim3(nc, (4 * HID) / 128, 3), 256>>>(d, i_lo, Wk, Wr);
        k_gate<<<dim3(nc, BH / 256), 256>>>(d, i_lo, b_lstm, out);
    }
}

// round 6
// speedup vs baseline: 2.7175x; 2.7154x over previous
#include <cuda_runtime.h>
#include <cuda_fp16.h>
#include <math.h>
#include <stdint.h>

#define S_LEN 32
#define T_LEN 32
#define BH    (64 * 512)           // [B,H] slab floats
#define Z4    (64 * 2048)          // [B,4H] slab floats
#define MAXC  32
#define KC    32                   // K-chunk per pipeline stage
#define LDA   40                   // halves per padded smem row (80B, 16B-aligned)
#define PLANE (128 * LDA)          // halves per plane (5120)
#define BUFH  (4 * PLANE)          // halves per buffer (Ahi,Alo,Bhi,Blo)
#define SMEM_DYN (2 * BUFH * 2)    // bytes (81920)

// ---------------- persistent device scratch ---------------------------------
__device__ __align__(16) float g_s_x[S_LEN * BH];
__device__ __align__(16) float g_s_h[S_LEN * BH];
__device__ __align__(16) float g_s_m[S_LEN * BH];
__device__ __align__(16) float g_t_x[T_LEN * BH];
__device__ __align__(16) float g_t_h[T_LEN * BH];
__device__ __align__(16) float g_t_m[T_LEN * BH];
__device__ __align__(16) float g_r  [MAXC * Z4];
__device__ __align__(16) float g_zs [MAXC * Z4];
__device__ __align__(16) float g_zt [MAXC * Z4];
// pre-split fp16 weights, K-major ([n][k])
__device__ __align__(16) __half g_WkT_hi[2048 * 512];
__device__ __align__(16) __half g_WkT_lo[2048 * 512];
__device__ __align__(16) __half g_WfT_hi[2048 * 1024];
__device__ __align__(16) __half g_WfT_lo[2048 * 1024];
__device__ __align__(16) float  g_bf[2048];

// ---------------- helpers ----------------------------------------------------
__device__ __forceinline__ void mma16816(float* c, const uint32_t* a,
                                         uint32_t b0, uint32_t b1) {
    asm volatile(
        "mma.sync.aligned.m16n8k16.row.col.f32.f16.f16.f32 "
        "{%0,%1,%2,%3}, {%4,%5,%6,%7}, {%8,%9}, {%0,%1,%2,%3};"
        : "+f"(c[0]), "+f"(c[1]), "+f"(c[2]), "+f"(c[3])
        : "r"(a[0]), "r"(a[1]), "r"(a[2]), "r"(a[3]), "r"(b0), "r"(b1));
}

// ---------------- init / prep ------------------------------------------------
__global__ void k_init(const float* __restrict__ src, const float* __restrict__ tgt)
{
    int idx = blockIdx.x * blockDim.x + threadIdx.x;
    g_s_x[idx] = src[idx];  g_s_h[idx] = 0.f;  g_s_m[idx] = 0.f;
    g_t_x[idx] = tgt[idx];  g_t_m[idx] = 0.f;  g_t_h[idx] = 0.f;
}

__global__ void k_prep_wk(const float* __restrict__ Wk)
{
    int g = blockIdx.x * blockDim.x + threadIdx.x;   // 2048*512
    int n = g & 2047, k = g >> 11;
    float v  = Wk[(size_t)k * 2048 + n];
    __half hi = __float2half_rn(v);
    __half lo = __float2half_rn(v - __half2float(hi));
    g_WkT_hi[(size_t)n * 512 + k] = hi;
    g_WkT_lo[(size_t)n * 512 + k] = lo;
}

// Wf[k][n] = sum_m WH2h[k][m] * Wr[m][n]  (fp32), stored split K-major
__global__ __launch_bounds__(256) void k_prep_wf(
    const float* __restrict__ WH2h, const float* __restrict__ Wr)
{
    __shared__ float Wh[32][33];
    __shared__ float Ws[32][33];
    const int n0 = blockIdx.x * 32, k0 = blockIdx.y * 32;
    const int t = threadIdx.x;
    const int nl = t & 31, kg = (t >> 5) * 4;
    float acc[4] = {0.f, 0.f, 0.f, 0.f};
    for (int m0 = 0; m0 < 512; m0 += 32) {
#pragma unroll
        for (int r = 0; r < 4; r++) {
            int idx = t + r * 256, a = idx >> 5, b = idx & 31;
            Wh[a][b] = WH2h[(size_t)(k0 + a) * 512 + m0 + b];
            Ws[a][b] = Wr  [(size_t)(m0 + a) * 2048 + n0 + b];
        }
        __syncthreads();
#pragma unroll
        for (int mm = 0; mm < 32; mm++) {
            float bv = Ws[mm][nl];
#pragma unroll
            for (int q = 0; q < 4; q++) acc[q] += Wh[kg + q][mm] * bv;
        }
        __syncthreads();
    }
#pragma unroll
    for (int q = 0; q < 4; q++) {
        __half hi = __float2half_rn(acc[q]);
        __half lo = __float2half_rn(acc[q] - __half2float(hi));
        size_t o = (size_t)(n0 + nl) * 1024 + (k0 + kg + q);
        g_WfT_hi[o] = hi;
        g_WfT_lo[o] = lo;
    }
}

__global__ void k_prep_b(const float* __restrict__ bH, const float* __restrict__ Wr,
                         const float* __restrict__ bl)
{
    int n = blockIdx.x * blockDim.x + threadIdx.x;
    float a = bl[n];
    for (int m = 0; m < 512; m++) a += bH[m] * Wr[(size_t)m * 2048 + n];
    g_bf[n] = a;
}

// ---------------- wavefront GEMM (mma.sync fp16 3-term) ----------------------
// grid: x = m-block (2 diagonal cells), y = n-tile (16 x 128), z = {0:r K=1024, 1:zs, 2:zt}
__global__ __launch_bounds__(256) void k_wave(int d, int i_lo, int nc)
{
    extern __shared__ __align__(16) __half smem[];

    const int tid  = threadIdx.x;
    const int wid  = tid >> 5;
    const int lane = tid & 31;
    const int warp_m = wid >> 2;    // 0..1  (64 rows each)
    const int warp_n = wid & 3;     // 0..3  (32 cols each)

    const int z  = blockIdx.z, nt_blk = blockIdx.y, mb = blockIdx.x;
    const int c0 = 2 * mb;
    int c1 = c0 + 1;  bool dup = false;
    if (c1 >= nc) { c1 = c0; dup = true; }
    const int i0 = i_lo + c0, j0 = d - i0, i1 = i_lo + c1, j1 = d - i1;
    const int K = (z == 0) ? 1024 : 512;
    const int C = K / KC;
    const int ntb = nt_blk * 128;

    const __half* Bhi_g = (z == 0) ? g_WfT_hi : g_WkT_hi;
    const __half* Blo_g = (z == 0) ? g_WfT_lo : g_WkT_lo;

    // ---- chunk loader ----
    auto load_chunk = [&](int c, int buf) {
        __half* dAhi = smem + buf * BUFH;
        __half* dAlo = dAhi + PLANE;
        __half* dBhi = dAhi + 2 * PLANE;
        __half* dBlo = dAhi + 3 * PLANE;
        const int k0 = c * KC;
        const float *h0, *h1;  int koff;
        if (z == 0) {
            if (k0 < 512) { h0 = g_s_h + (size_t)i0 * BH; h1 = g_s_h + (size_t)i1 * BH; }
            else          { h0 = g_t_h + (size_t)j0 * BH; h1 = g_t_h + (size_t)j1 * BH; }
            koff = k0 & 511;
        } else if (z == 1) { h0 = g_s_x + (size_t)i0 * BH; h1 = g_s_x + (size_t)i1 * BH; koff = k0; }
        else               { h0 = g_t_x + (size_t)j0 * BH; h1 = g_t_x + (size_t)j1 * BH; koff = k0; }

        // A: 128 rows x 32 floats, split to fp16 hi/lo
#pragma unroll
        for (int r4 = 0; r4 < 4; r4++) {
            const int idx = tid + r4 * 256;           // 0..1023
            const int row = idx >> 3;
            const int kq  = (idx & 7) * 4;
            const float* asrc = (row < 64) ? h0 : h1;
            float4 a = *(const float4*)(asrc + (size_t)(row & 63) * 512 + koff + kq);
            __half2 h01 = __floats2half2_rn(a.x, a.y);
            float2  f01 = __half22float2(h01);
            __half2 l01 = __floats2half2_rn(a.x - f01.x, a.y - f01.y);
            __half2 h23 = __floats2half2_rn(a.z, a.w);
            float2  f23 = __half22float2(h23);
            __half2 l23 = __floats2half2_rn(a.z - f23.x, a.w - f23.y);
            __half2* pa = (__half2*)(dAhi + row * LDA + kq);
            pa[0] = h01;  pa[1] = h23;
            __half2* pl = (__half2*)(dAlo + row * LDA + kq);
            pl[0] = l01;  pl[1] = l23;
        }
        // B: 128 rows x 32 halves per plane (pre-split in gmem), 8 halves per slot
#pragma unroll
        for (int r2 = 0; r2 < 2; r2++) {
            const int idx = tid + r2 * 256;           // 0..511
            const int row = idx >> 2;                 // 0..127
            const int kq  = (idx & 3) * 8;            // 0,8,16,24
            const size_t go = (size_t)(ntb + row) * K + k0 + kq;
            uint4 vh = *(const uint4*)(Bhi_g + go);
            uint4 vl = *(const uint4*)(Blo_g + go);
            *(uint4*)(dBhi + row * LDA + kq) = vh;
            *(uint4*)(dBlo + row * LDA + kq) = vl;
        }
    };

    float acc[4][4][4];
#pragma unroll
    for (int a = 0; a < 4; a++)
#pragma unroll
        for (int b = 0; b < 4; b++)
#pragma unroll
            for (int q = 0; q < 4; q++) acc[a][b][q] = 0.f;

    load_chunk(0, 0);
    __syncthreads();

    for (int c = 0; c < C; c++) {
        const int b = c & 1;
        if (c + 1 < C) load_chunk(c + 1, 1 - b);

        const __half* sAhi = smem + b * BUFH;
        const __half* sAlo = sAhi + PLANE;
        const __half* sBhi = sAhi + 2 * PLANE;
        const __half* sBlo = sAhi + 3 * PLANE;

#pragma unroll
        for (int ks = 0; ks < 2; ks++) {
            const int kb = ks * 16 + (lane & 3) * 2;
            uint32_t ah[4][4], al[4][4];
#pragma unroll
            for (int mt = 0; mt < 4; mt++) {
                const int r0 = warp_m * 64 + mt * 16 + (lane >> 2);
                ah[mt][0] = *(const uint32_t*)(sAhi + r0 * LDA + kb);
                ah[mt][1] = *(const uint32_t*)(sAhi + (r0 + 8) * LDA + kb);
                ah[mt][2] = *(const uint32_t*)(sAhi + r0 * LDA + kb + 8);
                ah[mt][3] = *(const uint32_t*)(sAhi + (r0 + 8) * LDA + kb + 8);
                al[mt][0] = *(const uint32_t*)(sAlo + r0 * LDA + kb);
                al[mt][1] = *(const uint32_t*)(sAlo + (r0 + 8) * LDA + kb);
                al[mt][2] = *(const uint32_t*)(sAlo + r0 * LDA + kb + 8);
                al[mt][3] = *(const uint32_t*)(sAlo + (r0 + 8) * LDA + kb + 8);
            }
            uint32_t bh[4][2], bl[4][2];
#pragma unroll
            for (int nt = 0; nt < 4; nt++) {
                const int n = warp_n * 32 + nt * 8 + (lane >> 2);
                bh[nt][0] = *(const uint32_t*)(sBhi + n * LDA + kb);
                bh[nt][1] = *(const uint32_t*)(sBhi + n * LDA + kb + 8);
                bl[nt][0] = *(const uint32_t*)(sBlo + n * LDA + kb);
                bl[nt][1] = *(const uint32_t*)(sBlo + n * LDA + kb + 8);
            }
#pragma unroll
            for (int mt = 0; mt < 4; mt++)
#pragma unroll
                for (int nt = 0; nt < 4; nt++) {
                    mma16816(acc[mt][nt], ah[mt], bh[nt][0], bh[nt][1]);
                    mma16816(acc[mt][nt], ah[mt], bl[nt][0], bl[nt][1]);
                    mma16816(acc[mt][nt], al[mt], bh[nt][0], bh[nt][1]);
                }
        }
        __syncthreads();
    }

    // ---- epilogue: direct fp32 stores (+ fused bias for z==0) ----
    float* Cbase = (z == 0) ? g_r : (z == 1) ? g_zs : g_zt;
#pragma unroll
    for (int mt = 0; mt < 4; mt++) {
        const int r0 = warp_m * 64 + mt * 16 + (lane >> 2);
#pragma unroll
        for (int nt = 0; nt < 4; nt++) {
            const int col = ntb + warp_n * 32 + nt * 8 + (lane & 3) * 2;
            float bx = 0.f, by = 0.f;
            if (z == 0) {
                float2 bb = *(const float2*)(g_bf + col);
                bx = bb.x;  by = bb.y;
            }
#pragma unroll
            for (int half_ = 0; half_ < 2; half_++) {
                const int r = r0 + half_ * 8;
                if (r >= 64 && dup) continue;
                const int cell = (r < 64) ? c0 : c1;
                float2 v;
                v.x = acc[mt][nt][half_ * 2]     + bx;
                v.y = acc[mt][nt][half_ * 2 + 1] + by;
                *(float2*)(Cbase + (size_t)cell * Z4 + (size_t)(r & 63) * 2048 + col) = v;
            }
        }
    }
}

// ---------------- gate + state update ----------------------------------------
__device__ __forceinline__ float sigmoidf(float x) { return 1.f / (1.f + __expf(-x)); }

__global__ __launch_bounds__(256) void k_gate(int d, int i_lo, float* __restrict__ out)
{
    const int ci  = blockIdx.x;
    const int i   = i_lo + ci;
    const int j   = d - i;
    const int idx = blockIdx.y * blockDim.x + threadIdx.x;   // [0, B*H)
    const int m   = idx >> 9;
    const int h   = idx & 511;

    const size_t base = (size_t)ci * Z4 + (size_t)m * 2048;
    const float rI = g_r[base + h];
    const float rF = g_r[base + 512 + h];
    const float rG = g_r[base + 1024 + h];
    const float rO = g_r[base + 1536 + h];

    {
        const float zi = g_zs[base + h]        + rI;
        const float zf = g_zs[base + 512 + h]  + rF;
        const float zg = g_zs[base + 1024 + h] + rG;
        const float zo = g_zs[base + 1536 + h] + rO;
        const size_t si = (size_t)i * BH + idx;
        const float c  = g_s_m[si];
        const float c2 = sigmoidf(zf) * c + sigmoidf(zi) * tanhf(zg);
        const float h2 = sigmoidf(zo) * tanhf(c2);
        g_s_m[si] = c2;  g_s_h[si] = h2;  g_s_x[si] = h2;
        if (j == T_LEN - 1) out[si] = h2;
    }
    {
        const float zi = g_zt[base + h]        + rI;
        const float zf = g_zt[base + 512 + h]  + rF;
        const float zg = g_zt[base + 1024 + h] + rG;
        const float zo = g_zt[base + 1536 + h] + rO;
        const size_t ti = (size_t)j * BH + idx;
        const float c  = g_t_m[ti];
        const float c2 = sigmoidf(zf) * c + sigmoidf(zi) * tanhf(zg);
        const float h2 = sigmoidf(zo) * tanhf(c2);
        g_t_m[ti] = c2;  g_t_h[ti] = h2;  g_t_x[ti] = h2;
        if (i == S_LEN - 1) out[(size_t)S_LEN * BH + ti] = h2;
    }
}

// ---------------- launch -----------------------------------------------------
extern "C" void kernel_launch(void* const* d_in, const int* in_sizes, int n_in,
                              void* d_out, int out_size)
{
    const float* source = (const float*)d_in[0];
    const float* target = (const float*)d_in[1];
    const float* W_H2h  = (const float*)d_in[2];
    const float* b_H2h  = (const float*)d_in[3];
    const float* Wk     = (const float*)d_in[4];
    const float* Wr     = (const float*)d_in[5];
    const float* b_lstm = (const float*)d_in[6];
    float* out = (float*)d_out;

    cudaFuncSetAttribute(k_wave, cudaFuncAttributeMaxDynamicSharedMemorySize, SMEM_DYN);

    k_init<<<(S_LEN * BH) / 256, 256>>>(source, target);
    k_prep_wk<<<(2048 * 512) / 256, 256>>>(Wk);
    k_prep_wf<<<dim3(64, 32), 256>>>(W_H2h, Wr);
    k_prep_b<<<8, 256>>>(b_H2h, Wr, b_lstm);

    for (int d = 0; d < S_LEN + T_LEN - 1; d++) {
        int i_lo = d - (T_LEN - 1); if (i_lo < 0) i_lo = 0;
        int i_hi = d; if (i_hi > S_LEN - 1) i_hi = S_LEN - 1;
        int nc  = i_hi - i_lo + 1;
        int mbs = (nc + 1) / 2;
        k_wave<<<dim3(mbs, 16, 3), 256, SMEM_DYN>>>(d, i_lo, nc);
        k_gate<<<dim3(nc, BH / 256), 256>>>(d, i_lo, out);
    }
}

// round 7
// speedup vs baseline: 3.3237x; 1.2231x over previous
#include <cuda_runtime.h>
#include <cuda_fp16.h>
#include <math.h>
#include <stdint.h>

#define S_LEN 32
#define T_LEN 32
#define BH    (64 * 512)
#define Z4    (64 * 2048)
#define MAXC  32
#define KC    32
#define LDA   40                   // halves per padded smem row (80B pitch)

// ---------------- persistent device scratch ---------------------------------
__device__ __align__(16) float g_s_x[S_LEN * BH];
__device__ __align__(16) float g_s_h[S_LEN * BH];
__device__ __align__(16) float g_s_m[S_LEN * BH];
__device__ __align__(16) float g_t_x[T_LEN * BH];
__device__ __align__(16) float g_t_h[T_LEN * BH];
__device__ __align__(16) float g_t_m[T_LEN * BH];
__device__ __align__(16) float g_r  [MAXC * Z4];
__device__ __align__(16) float g_zs [MAXC * Z4];
__device__ __align__(16) float g_zt [MAXC * Z4];
__device__ __align__(16) __half g_WkT_hi[2048 * 512];
__device__ __align__(16) __half g_WkT_lo[2048 * 512];
__device__ __align__(16) __half g_WfT_hi[2048 * 1024];
__device__ __align__(16) __half g_WfT_lo[2048 * 1024];
__device__ __align__(16) float  g_bf[2048];
__device__ __align__(16) float  g_bfp[16 * 2048];

// ---------------- helpers ----------------------------------------------------
__device__ __forceinline__ void mma16816(float* c, const uint32_t* a,
                                         uint32_t b0, uint32_t b1) {
    asm volatile(
        "mma.sync.aligned.m16n8k16.row.col.f32.f16.f16.f32 "
        "{%0,%1,%2,%3}, {%4,%5,%6,%7}, {%8,%9}, {%0,%1,%2,%3};"
        : "+f"(c[0]), "+f"(c[1]), "+f"(c[2]), "+f"(c[3])
        : "r"(a[0]), "r"(a[1]), "r"(a[2]), "r"(a[3]), "r"(b0), "r"(b1));
}
__device__ __forceinline__ void cp_async16(uint32_t saddr, const void* gptr) {
    asm volatile("cp.async.cg.shared.global [%0], [%1], 16;"
                 :: "r"(saddr), "l"(gptr) : "memory");
}
__device__ __forceinline__ void cp_commit() {
    asm volatile("cp.async.commit_group;" ::: "memory");
}
__device__ __forceinline__ void cp_wait0() {
    asm volatile("cp.async.wait_group 0;" ::: "memory");
}

// ---------------- init / prep ------------------------------------------------
__global__ void k_init(const float* __restrict__ src, const float* __restrict__ tgt)
{
    int idx = blockIdx.x * blockDim.x + threadIdx.x;
    g_s_x[idx] = src[idx];  g_s_h[idx] = 0.f;  g_s_m[idx] = 0.f;
    g_t_x[idx] = tgt[idx];  g_t_h[idx] = 0.f;  g_t_m[idx] = 0.f;
}

__global__ void k_prep_wk(const float* __restrict__ Wk)
{
    int g = blockIdx.x * blockDim.x + threadIdx.x;
    int n = g & 2047, k = g >> 11;
    float v  = Wk[(size_t)k * 2048 + n];
    __half hi = __float2half_rn(v);
    __half lo = __float2half_rn(v - __half2float(hi));
    g_WkT_hi[(size_t)n * 512 + k] = hi;
    g_WkT_lo[(size_t)n * 512 + k] = lo;
}

__global__ __launch_bounds__(256) void k_prep_wf(
    const float* __restrict__ WH2h, const float* __restrict__ Wr)
{
    __shared__ float Wh[32][33];
    __shared__ float Ws[32][33];
    const int n0 = blockIdx.x * 32, k0 = blockIdx.y * 32;
    const int t = threadIdx.x;
    const int nl = t & 31, kg = (t >> 5) * 4;
    float acc[4] = {0.f, 0.f, 0.f, 0.f};
    for (int m0 = 0; m0 < 512; m0 += 32) {
#pragma unroll
        for (int r = 0; r < 4; r++) {
            int idx = t + r * 256, a = idx >> 5, b = idx & 31;
            Wh[a][b] = WH2h[(size_t)(k0 + a) * 512 + m0 + b];
            Ws[a][b] = Wr  [(size_t)(m0 + a) * 2048 + n0 + b];
        }
        __syncthreads();
#pragma unroll
        for (int mm = 0; mm < 32; mm++) {
            float bv = Ws[mm][nl];
#pragma unroll
            for (int q = 0; q < 4; q++) acc[q] += Wh[kg + q][mm] * bv;
        }
        __syncthreads();
    }
#pragma unroll
    for (int q = 0; q < 4; q++) {
        __half hi = __float2half_rn(acc[q]);
        __half lo = __float2half_rn(acc[q] - __half2float(hi));
        size_t o = (size_t)(n0 + nl) * 1024 + (k0 + kg + q);
        g_WfT_hi[o] = hi;
        g_WfT_lo[o] = lo;
    }
}

// bias partials: grid (8, 16) x 256
__global__ void k_prep_b1(const float* __restrict__ bH, const float* __restrict__ Wr)
{
    int n = blockIdx.x * blockDim.x + threadIdx.x;
    int ch = blockIdx.y;
    float a = 0.f;
    for (int m = ch * 32; m < ch * 32 + 32; m++)
        a += bH[m] * Wr[(size_t)m * 2048 + n];
    g_bfp[ch * 2048 + n] = a;
}
__global__ void k_prep_b2(const float* __restrict__ bl)
{
    int n = blockIdx.x * blockDim.x + threadIdx.x;
    float a = bl[n];
#pragma unroll
    for (int c = 0; c < 16; c++) a += g_bfp[c * 2048 + n];
    g_bf[n] = a;
}

// ---------------- wavefront GEMM (mma.sync fp16 3-term) ----------------------
// MC = cells per m-block. grid: x = m-block, y = n-tile (16x128), z = {0:r,1:zs,2:zt}
template <int MC>
__global__ __launch_bounds__(256, 1) void k_wave(int d, int i_lo, int nc)
{
    constexpr int ROWS  = 64 * MC;
    constexpr int MT    = 2 * MC;            // 16-row tiles per warp (2 warp_m)
    constexpr int APL   = ROWS * LDA;        // halves per A plane
    constexpr int BPL   = 128 * LDA;
    constexpr int BUFH  = 2 * APL + 2 * BPL; // halves per buffer

    extern __shared__ __align__(16) __half smem[];

    const int tid  = threadIdx.x;
    const int wid  = tid >> 5;
    const int lane = tid & 31;
    const int warp_m = wid >> 2;    // 0..1, MT*16 rows each
    const int warp_n = wid & 3;     // 0..3, 32 cols each

    const int z  = blockIdx.z, nt_blk = blockIdx.y, mb = blockIdx.x;
    const int K = (z == 0) ? 1024 : 512;
    const int C = K / KC;
    const int ntb = nt_blk * 128;

    // per-group cell indices (clamped)
    int cell_i[MC], cell_j[MC];
#pragma unroll
    for (int g = 0; g < MC; g++) {
        int c = MC * mb + g; if (c > nc - 1) c = nc - 1;
        cell_i[g] = i_lo + c;
        cell_j[g] = d - cell_i[g];
    }

    const __half* Bhi_g = (z == 0) ? g_WfT_hi : g_WkT_hi;
    const __half* Blo_g = (z == 0) ? g_WfT_lo : g_WkT_lo;

    const uint32_t smem_u = (uint32_t)__cvta_generic_to_shared(smem);

    // ---- A gmem -> regs ----
    float4 Ra[2 * MC];
    auto lda_regs = [&](int c) {
        const int k0 = c * KC;
        int koff = (z == 0) ? (k0 & 511) : k0;
#pragma unroll
        for (int r = 0; r < 2 * MC; r++) {
            const int idx = tid + r * 256;
            const int row = idx >> 3;            // 0..ROWS-1
            const int kq  = (idx & 7) * 4;
            const int g   = row >> 6;
            const float* src;
            if (z == 0) src = (k0 < 512) ? (g_s_h + (size_t)cell_i[g] * BH)
                                         : (g_t_h + (size_t)cell_j[g] * BH);
            else if (z == 1) src = g_s_x + (size_t)cell_i[g] * BH;
            else             src = g_t_x + (size_t)cell_j[g] * BH;
            Ra[r] = *(const float4*)(src + (size_t)(row & 63) * 512 + koff + kq);
        }
    };
    // ---- B gmem -> smem (cp.async) ----
    auto ldb_async = [&](int c, int buf) {
        const int k0 = c * KC;
        const uint32_t dB = smem_u + (buf * BUFH + 2 * APL) * 2;  // bytes
#pragma unroll
        for (int r2 = 0; r2 < 2; r2++) {
            const int idx = tid + r2 * 256;      // 0..511
            const int row = idx >> 2;
            const int kq  = (idx & 3) * 8;
            const size_t go = (size_t)(ntb + row) * K + k0 + kq;
            const uint32_t so = (uint32_t)(row * LDA + kq) * 2;
            cp_async16(dB + so,            Bhi_g + go);
            cp_async16(dB + BPL * 2 + so,  Blo_g + go);
        }
        cp_commit();
    };
    // ---- A regs -> smem (split) ----
    auto sta = [&](int buf) {
        __half* dAhi = smem + buf * BUFH;
        __half* dAlo = dAhi + APL;
#pragma unroll
        for (int r = 0; r < 2 * MC; r++) {
            const int idx = tid + r * 256;
            const int row = idx >> 3;
            const int kq  = (idx & 7) * 4;
            float4 a = Ra[r];
            __half2 h01 = __floats2half2_rn(a.x, a.y);
            float2  f01 = __half22float2(h01);
            __half2 l01 = __floats2half2_rn(a.x - f01.x, a.y - f01.y);
            __half2 h23 = __floats2half2_rn(a.z, a.w);
            float2  f23 = __half22float2(h23);
            __half2 l23 = __floats2half2_rn(a.z - f23.x, a.w - f23.y);
            __half2* pa = (__half2*)(dAhi + row * LDA + kq);
            pa[0] = h01;  pa[1] = h23;
            __half2* pl = (__half2*)(dAlo + row * LDA + kq);
            pl[0] = l01;  pl[1] = l23;
        }
    };

    float acc[MT][4][4];
#pragma unroll
    for (int a = 0; a < MT; a++)
#pragma unroll
        for (int b = 0; b < 4; b++)
#pragma unroll
            for (int q = 0; q < 4; q++) acc[a][b][q] = 0.f;

    // prologue: chunk 0
    lda_regs(0);
    ldb_async(0, 0);
    sta(0);
    cp_wait0();
    __syncthreads();

    for (int c = 0; c < C; c++) {
        const int b = c & 1;
        if (c + 1 < C) {
            lda_regs(c + 1);          // LDG in flight during MMA
            ldb_async(c + 1, 1 - b);  // cp.async in flight during MMA
        }

        const __half* sAhi = smem + b * BUFH;
        const __half* sAlo = sAhi + APL;
        const __half* sBhi = sAhi + 2 * APL;
        const __half* sBlo = sBhi + BPL;

#pragma unroll
        for (int ks = 0; ks < 2; ks++) {
            const int kb = ks * 16 + (lane & 3) * 2;
            uint32_t bh[4][2], bl[4][2];
#pragma unroll
            for (int nt = 0; nt < 4; nt++) {
                const int n = warp_n * 32 + nt * 8 + (lane >> 2);
                bh[nt][0] = *(const uint32_t*)(sBhi + n * LDA + kb);
                bh[nt][1] = *(const uint32_t*)(sBhi + n * LDA + kb + 8);
                bl[nt][0] = *(const uint32_t*)(sBlo + n * LDA + kb);
                bl[nt][1] = *(const uint32_t*)(sBlo + n * LDA + kb + 8);
            }
#pragma unroll
            for (int mt = 0; mt < MT; mt++) {
                const int r0 = warp_m * (MT * 16) + mt * 16 + (lane >> 2);
                uint32_t ah[4], al[4];
                ah[0] = *(const uint32_t*)(sAhi + r0 * LDA + kb);
                ah[1] = *(const uint32_t*)(sAhi + (r0 + 8) * LDA + kb);
                ah[2] = *(const uint32_t*)(sAhi + r0 * LDA + kb + 8);
                ah[3] = *(const uint32_t*)(sAhi + (r0 + 8) * LDA + kb + 8);
                al[0] = *(const uint32_t*)(sAlo + r0 * LDA + kb);
                al[1] = *(const uint32_t*)(sAlo + (r0 + 8) * LDA + kb);
                al[2] = *(const uint32_t*)(sAlo + r0 * LDA + kb + 8);
                al[3] = *(const uint32_t*)(sAlo + (r0 + 8) * LDA + kb + 8);
#pragma unroll
                for (int nt = 0; nt < 4; nt++) {
                    mma16816(acc[mt][nt], ah, bh[nt][0], bh[nt][1]);
                    mma16816(acc[mt][nt], ah, bl[nt][0], bl[nt][1]);
                    mma16816(acc[mt][nt], al, bh[nt][0], bh[nt][1]);
                }
            }
        }
        if (c + 1 < C) {
            sta(1 - b);
            cp_wait0();
        }
        __syncthreads();
    }

    // ---- epilogue ----
    float* Cbase = (z == 0) ? g_r : (z == 1) ? g_zs : g_zt;
#pragma unroll
    for (int mt = 0; mt < MT; mt++) {
        const int r0 = warp_m * (MT * 16) + mt * 16 + (lane >> 2);
#pragma unroll
        for (int nt = 0; nt < 4; nt++) {
            const int col = ntb + warp_n * 32 + nt * 8 + (lane & 3) * 2;
            float bx = 0.f, by = 0.f;
            if (z == 0) {
                float2 bb = *(const float2*)(g_bf + col);
                bx = bb.x;  by = bb.y;
            }
#pragma unroll
            for (int half_ = 0; half_ < 2; half_++) {
                const int r = r0 + half_ * 8;
                const int cidx = MC * mb + (r >> 6);
                if (cidx >= nc) continue;
                float2 v;
                v.x = acc[mt][nt][half_ * 2]     + bx;
                v.y = acc[mt][nt][half_ * 2 + 1] + by;
                *(float2*)(Cbase + (size_t)cidx * Z4 + (size_t)(r & 63) * 2048 + col) = v;
            }
        }
    }
}

// ---------------- gate + state update ----------------------------------------
__device__ __forceinline__ float sigmoidf(float x) { return 1.f / (1.f + __expf(-x)); }

__global__ __launch_bounds__(256) void k_gate(int d, int i_lo, float* __restrict__ out)
{
    const int ci  = blockIdx.x;
    const int i   = i_lo + ci;
    const int j   = d - i;
    const int idx = blockIdx.y * blockDim.x + threadIdx.x;
    const int m   = idx >> 9;
    const int h   = idx & 511;

    const size_t base = (size_t)ci * Z4 + (size_t)m * 2048;
    const float rI = g_r[base + h];
    const float rF = g_r[base + 512 + h];
    const float rG = g_r[base + 1024 + h];
    const float rO = g_r[base + 1536 + h];

    {
        const float zi = g_zs[base + h]        + rI;
        const float zf = g_zs[base + 512 + h]  + rF;
        const float zg = g_zs[base + 1024 + h] + rG;
        const float zo = g_zs[base + 1536 + h] + rO;
        const size_t si = (size_t)i * BH + idx;
        const float c  = g_s_m[si];
        const float c2 = sigmoidf(zf) * c + sigmoidf(zi) * tanhf(zg);
        const float h2 = sigmoidf(zo) * tanhf(c2);
        g_s_m[si] = c2;  g_s_h[si] = h2;  g_s_x[si] = h2;
        if (j == T_LEN - 1) out[si] = h2;
    }
    {
        const float zi = g_zt[base + h]        + rI;
        const float zf = g_zt[base + 512 + h]  + rF;
        const float zg = g_zt[base + 1024 + h] + rG;
        const float zo = g_zt[base + 1536 + h] + rO;
        const size_t ti = (size_t)j * BH + idx;
        const float c  = g_t_m[ti];
        const float c2 = sigmoidf(zf) * c + sigmoidf(zi) * tanhf(zg);
        const float h2 = sigmoidf(zo) * tanhf(c2);
        g_t_m[ti] = c2;  g_t_h[ti] = h2;  g_t_x[ti] = h2;
        if (i == S_LEN - 1) out[(size_t)S_LEN * BH + ti] = h2;
    }
}

// ---------------- launch -----------------------------------------------------
extern "C" void kernel_launch(void* const* d_in, const int* in_sizes, int n_in,
                              void* d_out, int out_size)
{
    const float* source = (const float*)d_in[0];
    const float* target = (const float*)d_in[1];
    const float* W_H2h  = (const float*)d_in[2];
    const float* b_H2h  = (const float*)d_in[3];
    const float* Wk     = (const float*)d_in[4];
    const float* Wr     = (const float*)d_in[5];
    const float* b_lstm = (const float*)d_in[6];
    float* out = (float*)d_out;

    const int SMEM2 = 2 * (2 * 128 * LDA + 2 * 128 * LDA) * 2;  // 81920
    const int SMEM4 = 2 * (2 * 256 * LDA + 2 * 128 * LDA) * 2;  // 122880
    cudaFuncSetAttribute(k_wave<2>, cudaFuncAttributeMaxDynamicSharedMemorySize, SMEM2);
    cudaFuncSetAttribute(k_wave<4>, cudaFuncAttributeMaxDynamicSharedMemorySize, SMEM4);

    k_init<<<(S_LEN * BH) / 256, 256>>>(source, target);
    k_prep_wk<<<(2048 * 512) / 256, 256>>>(Wk);
    k_prep_wf<<<dim3(64, 32), 256>>>(W_H2h, Wr);
    k_prep_b1<<<dim3(8, 16), 256>>>(b_H2h, Wr);
    k_prep_b2<<<8, 256>>>(b_lstm);

    for (int d = 0; d < S_LEN + T_LEN - 1; d++) {
        int i_lo = d - (T_LEN - 1); if (i_lo < 0) i_lo = 0;
        int i_hi = d; if (i_hi > S_LEN - 1) i_hi = S_LEN - 1;
        int nc  = i_hi - i_lo + 1;
        if (nc >= 16) {
            int mbs = (nc + 3) / 4;
            k_wave<4><<<dim3(mbs, 16, 3), 256, SMEM4>>>(d, i_lo, nc);
        } else {
            int mbs = (nc + 1) / 2;
            k_wave<2><<<dim3(mbs, 16, 3), 256, SMEM2>>>(d, i_lo, nc);
        }
        k_gate<<<dim3(nc, BH / 256), 256>>>(d, i_lo, out);
    }
}